// round 13
// baseline (speedup 1.0000x reference)
#include <cuda_runtime.h>
#include <cuda_fp16.h>
#include <math.h>
#include <stdint.h>

typedef unsigned long long ull;
typedef unsigned int u32;

#define NP 1024
#define KK 32
#define TILES 8192
#define NPASS 4096
#define GRID_MAIN 296

// ---------------- device scratch ----------------
__device__ float g_scores[TILES*256];         // [tile][k][m]
__device__ float g_P[TILES*512];              // [tile][m*64+o]

__device__ __forceinline__ u32 h2pack(float a, float b) {
    __half2 h = __float22half2_rn(make_float2(a, b));
    return *(u32*)&h;
}
__device__ __forceinline__ void mma16(float* d, u32 a0, u32 a1, u32 a2, u32 a3,
                                      u32 b0, u32 b1) {
    asm volatile(
        "mma.sync.aligned.m16n8k16.row.col.f32.f16.f16.f32 "
        "{%0,%1,%2,%3}, {%4,%5,%6,%7}, {%8,%9}, {%0,%1,%2,%3};"
        : "+f"(d[0]), "+f"(d[1]), "+f"(d[2]), "+f"(d[3])
        : "r"(a0), "r"(a1), "r"(a2), "r"(a3), "r"(b0), "r"(b1));
}

// ---------------- single fused kernel ----------------
// smem u32 layout (23328 u32 = 93312 B):
//  sAu  [0,18432)      Wtop' (phase1) then A=W2' fp16: row (m*64+o) stride 36 u32
//  sFu  [18432,20736)  phase1: sCen scratch; mainloop: B fp16 staging
//  sS   [20736,21312)  scores fp32 [tl][m*36 + k]
//  sP   [21312,22400)  P fp32 [tl][m*68 + o]
//  sBnb [22400,22464)
//  wts  [22464,23328)  MLP weights (864 floats)
__global__ void __launch_bounds__(256, 2)
main_kernel(const float* __restrict__ feat, const float* __restrict__ pts,
    const float* __restrict__ w1, const float* __restrict__ g1, const float* __restrict__ be1,
    const float* __restrict__ w2, const float* __restrict__ g2, const float* __restrict__ be2,
    const float* __restrict__ w3, const float* __restrict__ g3, const float* __restrict__ be3,
    const float* __restrict__ w4, const float* __restrict__ b4,
    const float* __restrict__ wb, const float* __restrict__ bng,
    const float* __restrict__ bnb, float* __restrict__ out)
{
    extern __shared__ u32 smu[];
    u32*   sAu  = smu;
    u32*   sFu  = smu + 18432;
    float* sS   = (float*)(smu + 20736);
    float* sP   = (float*)(smu + 21312);
    float* sBnb = (float*)(smu + 22400);
    float* sw1q = (float*)(smu + 22464);
    float* sw2q = sw1q + 112;
    float* sw3q = sw2q + 256;
    float* sw4q = sw3q + 256;
    float* sc1q = sw4q + 128; float* sb1q = sc1q + 16;
    float* sc2q = sb1q + 16;  float* sb2q = sc2q + 16;
    float* sc3q = sb2q + 16;  float* sb3q = sc3q + 16;
    float* sb4q = sb3q + 16;

    int bid = blockIdx.x;
    int t = threadIdx.x;
    int w = t >> 5, lane = t & 31;
    int g = lane >> 2, tid = lane & 3;
    int oc = w & 3;
    int khalf = w >> 2;
    float inv = rsqrtf(1.f + 1e-5f);

    int cnt = (NPASS - 1 - bid)/GRID_MAIN + 1;   // 13 or 14

    // ---- load MLP weights + bnb ----
    if (t < 112) sw1q[t] = w1[t];
    if (t < 256) { sw2q[t] = w2[t]; sw3q[t] = w3[t]; }
    if (t < 128) sw4q[t] = w4[t];
    if (t < 16)  { sc1q[t] = g1[t]*inv; sb1q[t] = be1[t];
                   sc2q[t] = g2[t]*inv; sb2q[t] = be2[t];
                   sc3q[t] = g3[t]*inv; sb3q[t] = be3[t]; }
    if (t < 8)   sb4q[t] = b4[t];
    if (t < 64)  sBnb[t] = bnb[t];
    __syncthreads();

    // ================= Phase 0: scores for this CTA's tiles =================
    {
        int total_e = cnt*64;
        for (int e = t; e < total_e; e += 256) {
            int itp = e >> 6, local = e & 63;
            int tile = 2*(bid + itp*GRID_MAIN) + (local >> 5);
            int k = local & 31;
            int n = tile & 1023, b = tile >> 10;

            float xf[7]; float d2 = 0.f;
#pragma unroll
            for (int d = 0; d < 3; d++) {
                int base = ((b*3 + d)*NP + n)*KK;
                float x  = pts[base + k];
                float cx = pts[base];
                xf[d] = cx;
                float df = x - cx;
                xf[3 + d] = df;
                d2 += df*df;
            }
            xf[6] = sqrtf(d2);

            float h1[16];
#pragma unroll
            for (int i = 0; i < 16; i++) {
                float a = 0.f;
#pragma unroll
                for (int j = 0; j < 7; j++) a += sw1q[i*7 + j]*xf[j];
                h1[i] = fmaxf(a*sc1q[i] + sb1q[i], 0.f);
            }
            float h2[16];
#pragma unroll
            for (int i = 0; i < 16; i++) {
                float a = 0.f;
#pragma unroll
                for (int j = 0; j < 16; j++) a += sw2q[i*16 + j]*h1[j];
                h2[i] = fmaxf(a*sc2q[i] + sb2q[i], 0.f);
            }
            float h3[16];
#pragma unroll
            for (int i = 0; i < 16; i++) {
                float a = 0.f;
#pragma unroll
                for (int j = 0; j < 16; j++) a += sw3q[i*16 + j]*h2[j];
                h3[i] = fmaxf(a*sc3q[i] + sb3q[i], 0.f);
            }
            float s[8];
#pragma unroll
            for (int i = 0; i < 8; i++) {
                float a = sb4q[i];
#pragma unroll
                for (int j = 0; j < 16; j++) a += sw4q[i*16 + j]*h3[j];
                s[i] = a;
            }
            float mx = s[0];
#pragma unroll
            for (int i = 1; i < 8; i++) mx = fmaxf(mx, s[i]);
            float sum = 0.f;
#pragma unroll
            for (int i = 0; i < 8; i++) { s[i] = __expf(s[i] - mx); sum += s[i]; }
            float r = 1.f / sum;
            float4 v0 = make_float4(s[0]*r, s[1]*r, s[2]*r, s[3]*r);
            float4 v1 = make_float4(s[4]*r, s[5]*r, s[6]*r, s[7]*r);
            float* dst = g_scores + (size_t)tile*256 + k*8;
            ((float4*)dst)[0] = v0;
            ((float4*)dst)[1] = v1;
        }
    }

    // ================= Phase 1: P for this CTA's tiles (MMA) =================
    // build Wtop' fp16 in the A region
    for (int i = t; i < 32768; i += 256) {
        int c = i >> 9, row = i & 511;
        ((__half*)sAu)[row*72 + c] = __float2half_rn(wb[i] * bng[row & 63] * inv);
    }
    __syncthreads();

    u32* sCen = sFu;   // 640 u32 scratch, stride 20 per cp
#pragma unroll
    for (int bt = 0; bt < 2; bt++) {
        // gather cen pairs for up to 16 tiles (clamped)
#pragma unroll
        for (int j2 = 0; j2 < 2; j2++) {
            int u = t + j2*256;          // 0..511
            int cp = u >> 4, tl16 = u & 15;
            int itj = bt*8 + (tl16 >> 1);
            int itc = itj < cnt ? itj : cnt - 1;
            int tile = 2*(bid + itc*GRID_MAIN) + (tl16 & 1);
            int n = tile & 1023, b = tile >> 10;
            const float* fp0 = feat + ((size_t)(b*64 + 2*cp)*NP + n)*KK;
            sCen[cp*20 + tl16] = h2pack(fp0[0], fp0[NP*KK]);
        }
        __syncthreads();

        u32 bfp[4][2][2];
#pragma unroll
        for (int ks = 0; ks < 4; ks++)
#pragma unroll
            for (int nt = 0; nt < 2; nt++) {
                bfp[ks][nt][0] = sCen[(ks*8 + tid)*20 + nt*8 + g];
                bfp[ks][nt][1] = sCen[(ks*8 + tid + 4)*20 + nt*8 + g];
            }

#pragma unroll
        for (int rb2 = 0; rb2 < 4; rb2++) {
            int row = (w*4 + rb2)*16 + g;
            float acc[2][4] = {{0,0,0,0},{0,0,0,0}};
#pragma unroll
            for (int ks = 0; ks < 4; ks++) {
                const u32* ar = sAu + row*36 + ks*8 + tid;
                u32 a0 = ar[0], a2 = ar[4];
                u32 a1 = ar[8*36], a3 = ar[8*36 + 4];
                mma16(acc[0], a0, a1, a2, a3, bfp[ks][0][0], bfp[ks][0][1]);
                mma16(acc[1], a0, a1, a2, a3, bfp[ks][1][0], bfp[ks][1][1]);
            }
#pragma unroll
            for (int nt = 0; nt < 2; nt++) {
                int j = nt*8 + 2*tid;
                int itj = bt*8 + (j >> 1);
                if (itj < cnt) {
                    int tile = 2*(bid + itj*GRID_MAIN);   // j even; j+1 = tile+1
                    g_P[(size_t)tile*512 + row]             = acc[nt][0];
                    g_P[(size_t)(tile + 1)*512 + row]       = acc[nt][1];
                    g_P[(size_t)tile*512 + row + 8]         = acc[nt][2];
                    g_P[(size_t)(tile + 1)*512 + row + 8]   = acc[nt][3];
                }
            }
        }
        __syncthreads();
    }

    // ================= Phase 2: build A = fp16(W2') in smem =================
    for (int i = t; i < 32768; i += 256) {
        int c = i >> 9, row = i & 511;
        float v = (wb[i] + wb[i + 32768]) * bng[row & 63] * inv;
        ((__half*)sAu)[row*72 + c] = __float2half_rn(v);
    }
    __syncthreads();

    // ================= mainloop (R10 structure, 68.3us) =================
    float4 rfa[2], rfb[2]; float rs[2]; float rp[4];

    auto stage_ldg = [&](int pp) {
        int tile0 = pp*2; int b = tile0 >> 10; int n0 = tile0 & 1023;
        const float* fbase = feat + ((b*64)*NP + n0)*KK;
#pragma unroll
        for (int j = 0; j < 2; j++) {
            int u = t + j*256;
            int tl = u >> 8, rem = u & 255;
            int cp = rem >> 3, q4 = rem & 7;
            const float* pa = fbase + (2*cp)*NP*KK + tl*KK + q4*4;
            rfa[j] = *(const float4*)pa;
            rfb[j] = *(const float4*)(pa + NP*KK);
        }
#pragma unroll
        for (int j = 0; j < 2; j++) rs[j] = g_scores[(size_t)tile0*256 + t + j*256];
#pragma unroll
        for (int j = 0; j < 4; j++) rp[j] = g_P[(size_t)tile0*512 + t + j*256];
    };
    auto stage_sts = [&]() {
#pragma unroll
        for (int j = 0; j < 2; j++) {
            int u = t + j*256;
            int tl = u >> 8, rem = u & 255;
            int cp = rem >> 3, q4 = rem & 7;
            u32* dst = sFu + cp*72 + tl*KK + q4*4;
            float4 fa = rfa[j], fb = rfb[j];
            dst[0] = h2pack(fa.x, fb.x);
            dst[1] = h2pack(fa.y, fb.y);
            dst[2] = h2pack(fa.z, fb.z);
            dst[3] = h2pack(fa.w, fb.w);
        }
#pragma unroll
        for (int j = 0; j < 2; j++) {
            int idx = t + j*256;            // tl*256 + k*8 + m
            int tl = idx >> 8, rem = idx & 255;
            int k = rem >> 3, m = rem & 7;
            sS[tl*288 + m*36 + k] = rs[j];
        }
#pragma unroll
        for (int j = 0; j < 4; j++) {
            int idx = t + j*256;            // tl*512 + m*64 + o
            int tl = idx >> 9, rem = idx & 511;
            int m = rem >> 6, o = rem & 63;
            sP[tl*544 + m*68 + o] = rp[j];
        }
    };

    stage_ldg(bid);

    int cp2 = bid;
    for (int it = 0; it < cnt; it++, cp2 += GRID_MAIN) {
        stage_sts();
        __syncthreads();
        if (it + 1 < cnt) stage_ldg(cp2 + GRID_MAIN);   // overlaps compute

        int tile0 = cp2*2;
        int b = tile0 >> 10, n0 = tile0 & 1023;
        int o0 = oc*16 + g;

        u32 bf[4][2][2][2];   // [ks][tl][nt][2]
#pragma unroll
        for (int ks = 0; ks < 4; ks++)
#pragma unroll
            for (int tl = 0; tl < 2; tl++)
#pragma unroll
                for (int nt = 0; nt < 2; nt++) {
                    int kcol = tl*KK + khalf*16 + nt*8 + g;
                    bf[ks][tl][nt][0] = sFu[(ks*8 + tid)*72 + kcol];
                    bf[ks][tl][nt][1] = sFu[(ks*8 + tid + 4)*72 + kcol];
                }

        float oacc[2][2][4];
#pragma unroll
        for (int tl = 0; tl < 2; tl++)
#pragma unroll
            for (int nt = 0; nt < 2; nt++)
#pragma unroll
                for (int r = 0; r < 4; r++) oacc[tl][nt][r] = 0.f;

#pragma unroll
        for (int mt = 0; mt < 8; mt++) {
            float acc[2][2][4];
#pragma unroll
            for (int tl = 0; tl < 2; tl++)
#pragma unroll
                for (int nt = 0; nt < 2; nt++)
#pragma unroll
                    for (int r = 0; r < 4; r++) acc[tl][nt][r] = 0.f;

            int row = mt*64 + o0;
#pragma unroll
            for (int ks = 0; ks < 4; ks++) {
                const u32* ar = sAu + row*36 + ks*8 + tid;
                u32 a0 = ar[0], a2 = ar[4];
                u32 a1 = ar[8*36], a3 = ar[8*36 + 4];
                mma16(acc[0][0], a0, a1, a2, a3, bf[ks][0][0][0], bf[ks][0][0][1]);
                mma16(acc[0][1], a0, a1, a2, a3, bf[ks][0][1][0], bf[ks][0][1][1]);
                mma16(acc[1][0], a0, a1, a2, a3, bf[ks][1][0][0], bf[ks][1][0][1]);
                mma16(acc[1][1], a0, a1, a2, a3, bf[ks][1][1][0], bf[ks][1][1][1]);
            }
#pragma unroll
            for (int tl = 0; tl < 2; tl++) {
                const float* srow = sS + tl*288 + mt*36 + khalf*16 + tid*2;
                float2 s0 = *(const float2*)(srow);
                float2 s1 = *(const float2*)(srow + 8);
                float p0 = sP[tl*544 + mt*68 + o0];
                float p1 = sP[tl*544 + mt*68 + o0 + 8];
                oacc[tl][0][0] += (acc[tl][0][0] - p0)*s0.x;
                oacc[tl][0][1] += (acc[tl][0][1] - p0)*s0.y;
                oacc[tl][0][2] += (acc[tl][0][2] - p1)*s0.x;
                oacc[tl][0][3] += (acc[tl][0][3] - p1)*s0.y;
                oacc[tl][1][0] += (acc[tl][1][0] - p0)*s1.x;
                oacc[tl][1][1] += (acc[tl][1][1] - p0)*s1.y;
                oacc[tl][1][2] += (acc[tl][1][2] - p1)*s1.x;
                oacc[tl][1][3] += (acc[tl][1][3] - p1)*s1.y;
            }
        }

        float b0 = sBnb[o0], b1 = sBnb[o0 + 8];
#pragma unroll
        for (int tl = 0; tl < 2; tl++) {
            int n = n0 + tl;
            float* ob = out + ((b*64 + o0)*NP + n)*KK + khalf*16 + tid*2;
#pragma unroll
            for (int nt = 0; nt < 2; nt++) {
                float2 r0 = make_float2(fmaxf(oacc[tl][nt][0] + b0, 0.f),
                                        fmaxf(oacc[tl][nt][1] + b0, 0.f));
                float2 r1 = make_float2(fmaxf(oacc[tl][nt][2] + b1, 0.f),
                                        fmaxf(oacc[tl][nt][3] + b1, 0.f));
                *(float2*)(ob + nt*8) = r0;
                *(float2*)(ob + 8*NP*KK + nt*8) = r1;
            }
        }
        __syncthreads();
    }
}

// ---------------- launch ----------------
extern "C" void kernel_launch(void* const* d_in, const int* in_sizes, int n_in,
                              void* d_out, int out_size)
{
    const float* features = (const float*)d_in[0];
    const float* pts      = (const float*)d_in[1];
    const float* w1  = (const float*)d_in[2];
    const float* g1  = (const float*)d_in[3];
    const float* be1 = (const float*)d_in[4];
    const float* w2  = (const float*)d_in[5];
    const float* g2  = (const float*)d_in[6];
    const float* be2 = (const float*)d_in[7];
    const float* w3  = (const float*)d_in[8];
    const float* g3  = (const float*)d_in[9];
    const float* be3 = (const float*)d_in[10];
    const float* w4  = (const float*)d_in[11];
    const float* b4  = (const float*)d_in[12];
    const float* wb  = (const float*)d_in[13];
    const float* bng = (const float*)d_in[14];
    const float* bnb = (const float*)d_in[15];
    float* out = (float*)d_out;

    const int MAIN_SMEM = 23328*4;   // 93312
    cudaFuncSetAttribute(main_kernel, cudaFuncAttributeMaxDynamicSharedMemorySize, MAIN_SMEM);

    main_kernel<<<GRID_MAIN, 256, MAIN_SMEM>>>(features, pts,
        w1, g1, be1, w2, g2, be2, w3, g3, be3, w4, b4, wb, bng, bnb, out);
}

// round 14
// speedup vs baseline: 1.0017x; 1.0017x over previous
#include <cuda_runtime.h>
#include <cuda_fp16.h>
#include <math.h>
#include <stdint.h>

typedef unsigned long long ull;
typedef unsigned int u32;

#define NP 1024
#define KK 32
#define TILES 8192
#define NPASS 4096
#define GRID_MAIN 296

// ---------------- device scratch ----------------
__device__ float g_scores[TILES*256];         // [tile][k][m]
__device__ float g_P[TILES*512];              // [tile][m*64+o]

__device__ __forceinline__ u32 h2pack(float a, float b) {
    __half2 h = __float22half2_rn(make_float2(a, b));
    return *(u32*)&h;
}
__device__ __forceinline__ void mma16(float* d, u32 a0, u32 a1, u32 a2, u32 a3,
                                      u32 b0, u32 b1) {
    asm volatile(
        "mma.sync.aligned.m16n8k16.row.col.f32.f16.f16.f32 "
        "{%0,%1,%2,%3}, {%4,%5,%6,%7}, {%8,%9}, {%0,%1,%2,%3};"
        : "+f"(d[0]), "+f"(d[1]), "+f"(d[2]), "+f"(d[3])
        : "r"(a0), "r"(a1), "r"(a2), "r"(a3), "r"(b0), "r"(b1));
}

// ---------------- single fused kernel, contiguous tile chunks ----------------
// smem u32 layout (23328 u32 = 93312 B):
//  sAu  [0,18432)      Wtop' (phase1) then A=W2' fp16: row (m*64+o) stride 36 u32
//  sFu  [18432,20736)  phase1: sCen scratch; mainloop: B fp16 staging
//  sS   [20736,21312)  scores fp32 [tl][m*36 + k]
//  sP   [21312,22400)  P fp32 [tl][m*68 + o]
//  sBnb [22400,22464)
//  wts  [22464,23328)  MLP weights (864 floats)
__global__ void __launch_bounds__(256, 2)
main_kernel(const float* __restrict__ feat, const float* __restrict__ pts,
    const float* __restrict__ w1, const float* __restrict__ g1, const float* __restrict__ be1,
    const float* __restrict__ w2, const float* __restrict__ g2, const float* __restrict__ be2,
    const float* __restrict__ w3, const float* __restrict__ g3, const float* __restrict__ be3,
    const float* __restrict__ w4, const float* __restrict__ b4,
    const float* __restrict__ wb, const float* __restrict__ bng,
    const float* __restrict__ bnb, float* __restrict__ out)
{
    extern __shared__ u32 smu[];
    u32*   sAu  = smu;
    u32*   sFu  = smu + 18432;
    float* sS   = (float*)(smu + 20736);
    float* sP   = (float*)(smu + 21312);
    float* sBnb = (float*)(smu + 22400);
    float* sw1q = (float*)(smu + 22464);
    float* sw2q = sw1q + 112;
    float* sw3q = sw2q + 256;
    float* sw4q = sw3q + 256;
    float* sc1q = sw4q + 128; float* sb1q = sc1q + 16;
    float* sc2q = sb1q + 16;  float* sb2q = sc2q + 16;
    float* sc3q = sb2q + 16;  float* sb3q = sc3q + 16;
    float* sb4q = sb3q + 16;

    int bid = blockIdx.x;
    int t = threadIdx.x;
    int w = t >> 5, lane = t & 31;
    int g = lane >> 2, tid = lane & 3;
    int oc = w & 3;
    int khalf = w >> 2;
    float inv = rsqrtf(1.f + 1e-5f);

    // contiguous pass chunk: 4096 = 248*14 + 48*13
    int cnt   = bid < 248 ? 14 : 13;
    int start = bid*13 + (bid < 248 ? bid : 248);
    int tstart = 2*start;                 // first tile
    int tcount = 2*cnt;                   // tiles owned (26 or 28)

    // ---- load MLP weights + bnb ----
    if (t < 112) sw1q[t] = w1[t];
    if (t < 256) { sw2q[t] = w2[t]; sw3q[t] = w3[t]; }
    if (t < 128) sw4q[t] = w4[t];
    if (t < 16)  { sc1q[t] = g1[t]*inv; sb1q[t] = be1[t];
                   sc2q[t] = g2[t]*inv; sb2q[t] = be2[t];
                   sc3q[t] = g3[t]*inv; sb3q[t] = be3[t]; }
    if (t < 8)   sb4q[t] = b4[t];
    if (t < 64)  sBnb[t] = bnb[t];
    __syncthreads();

    // ================= Phase 0: scores for this CTA's tiles (contiguous) ====
    {
        int total_e = tcount*32;
        for (int e = t; e < total_e; e += 256) {
            int tile = tstart + (e >> 5);
            int k = e & 31;
            int n = tile & 1023, b = tile >> 10;

            float xf[7]; float d2 = 0.f;
#pragma unroll
            for (int d = 0; d < 3; d++) {
                int base = ((b*3 + d)*NP + n)*KK;
                float x  = pts[base + k];
                float cx = pts[base];
                xf[d] = cx;
                float df = x - cx;
                xf[3 + d] = df;
                d2 += df*df;
            }
            xf[6] = sqrtf(d2);

            float h1[16];
#pragma unroll
            for (int i = 0; i < 16; i++) {
                float a = 0.f;
#pragma unroll
                for (int j = 0; j < 7; j++) a += sw1q[i*7 + j]*xf[j];
                h1[i] = fmaxf(a*sc1q[i] + sb1q[i], 0.f);
            }
            float h2[16];
#pragma unroll
            for (int i = 0; i < 16; i++) {
                float a = 0.f;
#pragma unroll
                for (int j = 0; j < 16; j++) a += sw2q[i*16 + j]*h1[j];
                h2[i] = fmaxf(a*sc2q[i] + sb2q[i], 0.f);
            }
            float h3[16];
#pragma unroll
            for (int i = 0; i < 16; i++) {
                float a = 0.f;
#pragma unroll
                for (int j = 0; j < 16; j++) a += sw3q[i*16 + j]*h2[j];
                h3[i] = fmaxf(a*sc3q[i] + sb3q[i], 0.f);
            }
            float s[8];
#pragma unroll
            for (int i = 0; i < 8; i++) {
                float a = sb4q[i];
#pragma unroll
                for (int j = 0; j < 16; j++) a += sw4q[i*16 + j]*h3[j];
                s[i] = a;
            }
            float mx = s[0];
#pragma unroll
            for (int i = 1; i < 8; i++) mx = fmaxf(mx, s[i]);
            float sum = 0.f;
#pragma unroll
            for (int i = 0; i < 8; i++) { s[i] = __expf(s[i] - mx); sum += s[i]; }
            float r = 1.f / sum;
            float4 v0 = make_float4(s[0]*r, s[1]*r, s[2]*r, s[3]*r);
            float4 v1 = make_float4(s[4]*r, s[5]*r, s[6]*r, s[7]*r);
            float* dst = g_scores + (size_t)tile*256 + k*8;
            ((float4*)dst)[0] = v0;
            ((float4*)dst)[1] = v1;
        }
    }

    // ================= Phase 1: P for this CTA's tiles (MMA, contiguous) ====
    for (int i = t; i < 32768; i += 256) {
        int c = i >> 9, row = i & 511;
        ((__half*)sAu)[row*72 + c] = __float2half_rn(wb[i] * bng[row & 63] * inv);
    }
    __syncthreads();

    u32* sCen = sFu;   // stride 20 per cp
#pragma unroll
    for (int bt = 0; bt < 2; bt++) {
        int tbase = tstart + bt*16;
        // gather cen pairs for 16 contiguous tiles (clamped at chunk end)
#pragma unroll
        for (int j2 = 0; j2 < 2; j2++) {
            int u = t + j2*256;          // 0..511
            int cp = u >> 4, tl16 = u & 15;
            int off = bt*16 + tl16;
            int tile = tstart + (off < tcount ? off : tcount - 1);
            int n = tile & 1023, b = tile >> 10;
            const float* fp0 = feat + ((size_t)(b*64 + 2*cp)*NP + n)*KK;
            sCen[cp*20 + tl16] = h2pack(fp0[0], fp0[NP*KK]);
        }
        __syncthreads();

        u32 bfp[4][2][2];
#pragma unroll
        for (int ks = 0; ks < 4; ks++)
#pragma unroll
            for (int nt = 0; nt < 2; nt++) {
                bfp[ks][nt][0] = sCen[(ks*8 + tid)*20 + nt*8 + g];
                bfp[ks][nt][1] = sCen[(ks*8 + tid + 4)*20 + nt*8 + g];
            }

#pragma unroll
        for (int rb2 = 0; rb2 < 4; rb2++) {
            int row = (w*4 + rb2)*16 + g;
            float acc[2][4] = {{0,0,0,0},{0,0,0,0}};
#pragma unroll
            for (int ks = 0; ks < 4; ks++) {
                const u32* ar = sAu + row*36 + ks*8 + tid;
                u32 a0 = ar[0], a2 = ar[4];
                u32 a1 = ar[8*36], a3 = ar[8*36 + 4];
                mma16(acc[0], a0, a1, a2, a3, bfp[ks][0][0], bfp[ks][0][1]);
                mma16(acc[1], a0, a1, a2, a3, bfp[ks][1][0], bfp[ks][1][1]);
            }
#pragma unroll
            for (int nt = 0; nt < 2; nt++) {
                int off = bt*16 + nt*8 + 2*tid;        // even
                if (off < tcount) {
                    size_t tcol = (size_t)(tbase + nt*8 + 2*tid);
                    g_P[tcol*512 + row]           = acc[nt][0];
                    g_P[(tcol + 1)*512 + row]     = acc[nt][1];
                    g_P[tcol*512 + row + 8]       = acc[nt][2];
                    g_P[(tcol + 1)*512 + row + 8] = acc[nt][3];
                }
            }
        }
        __syncthreads();
    }

    // ================= Phase 2: build A = fp16(W2') in smem =================
    for (int i = t; i < 32768; i += 256) {
        int c = i >> 9, row = i & 511;
        float v = (wb[i] + wb[i + 32768]) * bng[row & 63] * inv;
        ((__half*)sAu)[row*72 + c] = __float2half_rn(v);
    }
    __syncthreads();

    // ================= mainloop (R10 structure, contiguous passes) ==========
    float4 rfa[2], rfb[2]; float rs[2]; float rp[4];

    auto stage_ldg = [&](int pp) {
        int tile0 = pp*2; int b = tile0 >> 10; int n0 = tile0 & 1023;
        const float* fbase = feat + ((b*64)*NP + n0)*KK;
#pragma unroll
        for (int j = 0; j < 2; j++) {
            int u = t + j*256;
            int tl = u >> 8, rem = u & 255;
            int cp = rem >> 3, q4 = rem & 7;
            const float* pa = fbase + (2*cp)*NP*KK + tl*KK + q4*4;
            rfa[j] = *(const float4*)pa;
            rfb[j] = *(const float4*)(pa + NP*KK);
        }
#pragma unroll
        for (int j = 0; j < 2; j++) rs[j] = g_scores[(size_t)tile0*256 + t + j*256];
#pragma unroll
        for (int j = 0; j < 4; j++) rp[j] = g_P[(size_t)tile0*512 + t + j*256];
    };
    auto stage_sts = [&]() {
#pragma unroll
        for (int j = 0; j < 2; j++) {
            int u = t + j*256;
            int tl = u >> 8, rem = u & 255;
            int cp = rem >> 3, q4 = rem & 7;
            u32* dst = sFu + cp*72 + tl*KK + q4*4;
            float4 fa = rfa[j], fb = rfb[j];
            dst[0] = h2pack(fa.x, fb.x);
            dst[1] = h2pack(fa.y, fb.y);
            dst[2] = h2pack(fa.z, fb.z);
            dst[3] = h2pack(fa.w, fb.w);
        }
#pragma unroll
        for (int j = 0; j < 2; j++) {
            int idx = t + j*256;            // tl*256 + k*8 + m
            int tl = idx >> 8, rem = idx & 255;
            int k = rem >> 3, m = rem & 7;
            sS[tl*288 + m*36 + k] = rs[j];
        }
#pragma unroll
        for (int j = 0; j < 4; j++) {
            int idx = t + j*256;            // tl*512 + m*64 + o
            int tl = idx >> 9, rem = idx & 511;
            int m = rem >> 6, o = rem & 63;
            sP[tl*544 + m*68 + o] = rp[j];
        }
    };

    stage_ldg(start);

    for (int it = 0; it < cnt; it++) {
        int cp2 = start + it;
        stage_sts();
        __syncthreads();
        if (it + 1 < cnt) stage_ldg(cp2 + 1);   // overlaps compute

        int tile0 = cp2*2;
        int b = tile0 >> 10, n0 = tile0 & 1023;
        int o0 = oc*16 + g;

        u32 bf[4][2][2][2];   // [ks][tl][nt][2]
#pragma unroll
        for (int ks = 0; ks < 4; ks++)
#pragma unroll
            for (int tl = 0; tl < 2; tl++)
#pragma unroll
                for (int nt = 0; nt < 2; nt++) {
                    int kcol = tl*KK + khalf*16 + nt*8 + g;
                    bf[ks][tl][nt][0] = sFu[(ks*8 + tid)*72 + kcol];
                    bf[ks][tl][nt][1] = sFu[(ks*8 + tid + 4)*72 + kcol];
                }

        float oacc[2][2][4];
#pragma unroll
        for (int tl = 0; tl < 2; tl++)
#pragma unroll
            for (int nt = 0; nt < 2; nt++)
#pragma unroll
                for (int r = 0; r < 4; r++) oacc[tl][nt][r] = 0.f;

#pragma unroll
        for (int mt = 0; mt < 8; mt++) {
            float acc[2][2][4];
#pragma unroll
            for (int tl = 0; tl < 2; tl++)
#pragma unroll
                for (int nt = 0; nt < 2; nt++)
#pragma unroll
                    for (int r = 0; r < 4; r++) acc[tl][nt][r] = 0.f;

            int row = mt*64 + o0;
#pragma unroll
            for (int ks = 0; ks < 4; ks++) {
                const u32* ar = sAu + row*36 + ks*8 + tid;
                u32 a0 = ar[0], a2 = ar[4];
                u32 a1 = ar[8*36], a3 = ar[8*36 + 4];
                mma16(acc[0][0], a0, a1, a2, a3, bf[ks][0][0][0], bf[ks][0][0][1]);
                mma16(acc[0][1], a0, a1, a2, a3, bf[ks][0][1][0], bf[ks][0][1][1]);
                mma16(acc[1][0], a0, a1, a2, a3, bf[ks][1][0][0], bf[ks][1][0][1]);
                mma16(acc[1][1], a0, a1, a2, a3, bf[ks][1][1][0], bf[ks][1][1][1]);
            }
#pragma unroll
            for (int tl = 0; tl < 2; tl++) {
                const float* srow = sS + tl*288 + mt*36 + khalf*16 + tid*2;
                float2 s0 = *(const float2*)(srow);
                float2 s1 = *(const float2*)(srow + 8);
                float p0 = sP[tl*544 + mt*68 + o0];
                float p1 = sP[tl*544 + mt*68 + o0 + 8];
                oacc[tl][0][0] += (acc[tl][0][0] - p0)*s0.x;
                oacc[tl][0][1] += (acc[tl][0][1] - p0)*s0.y;
                oacc[tl][0][2] += (acc[tl][0][2] - p1)*s0.x;
                oacc[tl][0][3] += (acc[tl][0][3] - p1)*s0.y;
                oacc[tl][1][0] += (acc[tl][1][0] - p0)*s1.x;
                oacc[tl][1][1] += (acc[tl][1][1] - p0)*s1.y;
                oacc[tl][1][2] += (acc[tl][1][2] - p1)*s1.x;
                oacc[tl][1][3] += (acc[tl][1][3] - p1)*s1.y;
            }
        }

        float b0 = sBnb[o0], b1 = sBnb[o0 + 8];
#pragma unroll
        for (int tl = 0; tl < 2; tl++) {
            int n = n0 + tl;
            float* ob = out + ((b*64 + o0)*NP + n)*KK + khalf*16 + tid*2;
#pragma unroll
            for (int nt = 0; nt < 2; nt++) {
                float2 r0 = make_float2(fmaxf(oacc[tl][nt][0] + b0, 0.f),
                                        fmaxf(oacc[tl][nt][1] + b0, 0.f));
                float2 r1 = make_float2(fmaxf(oacc[tl][nt][2] + b1, 0.f),
                                        fmaxf(oacc[tl][nt][3] + b1, 0.f));
                *(float2*)(ob + nt*8) = r0;
                *(float2*)(ob + 8*NP*KK + nt*8) = r1;
            }
        }
        __syncthreads();
    }
}

// ---------------- launch ----------------
extern "C" void kernel_launch(void* const* d_in, const int* in_sizes, int n_in,
                              void* d_out, int out_size)
{
    const float* features = (const float*)d_in[0];
    const float* pts      = (const float*)d_in[1];
    const float* w1  = (const float*)d_in[2];
    const float* g1  = (const float*)d_in[3];
    const float* be1 = (const float*)d_in[4];
    const float* w2  = (const float*)d_in[5];
    const float* g2  = (const float*)d_in[6];
    const float* be2 = (const float*)d_in[7];
    const float* w3  = (const float*)d_in[8];
    const float* g3  = (const float*)d_in[9];
    const float* be3 = (const float*)d_in[10];
    const float* w4  = (const float*)d_in[11];
    const float* b4  = (const float*)d_in[12];
    const float* wb  = (const float*)d_in[13];
    const float* bng = (const float*)d_in[14];
    const float* bnb = (const float*)d_in[15];
    float* out = (float*)d_out;

    const int MAIN_SMEM = 23328*4;   // 93312
    cudaFuncSetAttribute(main_kernel, cudaFuncAttributeMaxDynamicSharedMemorySize, MAIN_SMEM);

    main_kernel<<<GRID_MAIN, 256, MAIN_SMEM>>>(features, pts,
        w1, g1, be1, w2, g2, be2, w3, g3, be3, w4, b4, wb, bng, bnb, out);
}

// round 15
// speedup vs baseline: 3.3014x; 3.2958x over previous
#include <cuda_runtime.h>
#include <cuda_fp16.h>
#include <math.h>
#include <stdint.h>

typedef unsigned long long ull;
typedef unsigned int u32;

#define NP 1024
#define KK 32
#define TILES 8192
#define NPASS 4096
#define GRID_MAIN 296
#define PMMA_BLKS 128
#define SCORE_BLKS 512
#define PRE_GRID (PMMA_BLKS + SCORE_BLKS)   // 640

// ---------------- device scratch ----------------
__device__ __align__(16) __half g_Ah[512*72];   // W2'  fp16, rows m*64+o, stride 72
__device__ __align__(16) __half g_Atop[512*72]; // Wtop' fp16, same layout
__device__ float g_scores[TILES*256];           // [tile][k][m]
__device__ float g_P[TILES*512];                // [tile][m*64+o]

__device__ __forceinline__ u32 h2pack(float a, float b) {
    __half2 h = __float22half2_rn(make_float2(a, b));
    return *(u32*)&h;
}
__device__ __forceinline__ void mma16(float* d, u32 a0, u32 a1, u32 a2, u32 a3,
                                      u32 b0, u32 b1) {
    asm volatile(
        "mma.sync.aligned.m16n8k16.row.col.f32.f16.f16.f32 "
        "{%0,%1,%2,%3}, {%4,%5,%6,%7}, {%8,%9}, {%0,%1,%2,%3};"
        : "+f"(d[0]), "+f"(d[1]), "+f"(d[2]), "+f"(d[3])
        : "r"(a0), "r"(a1), "r"(a2), "r"(a3), "r"(b0), "r"(b1));
}

// =================== prep: build g_Ah + g_Atop once ===================
__global__ void prep_kernel(const float* __restrict__ wb, const float* __restrict__ bng) {
    int i = blockIdx.x*256 + threadIdx.x;      // i = c*512 + row,  row = m*64+o
    int c = i >> 9, row = i & 511;
    float sc = bng[row & 63] * rsqrtf(1.f + 1e-5f);
    float top = wb[i] * sc;
    float both = (wb[i] + wb[i + 32768]) * sc;
    g_Atop[row*72 + c] = __float2half_rn(top);
    g_Ah[row*72 + c]   = __float2half_rn(both);
}

// =================== pre kernel: pmma (W copied from g_Atop) + scores ===================
__global__ void __launch_bounds__(512, 2)
pre_kernel(const float* __restrict__ feat, const float* __restrict__ pts,
    const float* __restrict__ w1, const float* __restrict__ g1, const float* __restrict__ be1,
    const float* __restrict__ w2, const float* __restrict__ g2, const float* __restrict__ be2,
    const float* __restrict__ w3, const float* __restrict__ g3, const float* __restrict__ be3,
    const float* __restrict__ w4, const float* __restrict__ b4)
{
    __shared__ __align__(16) u32 spre[11776];   // 47104 B
    int bid = blockIdx.x;
    int t = threadIdx.x;
    float inv = rsqrtf(1.f + 1e-5f);

    if (bid >= PMMA_BLKS) {       // ---- scores ----
        float* sw1 = (float*)spre;
        float* sw2 = sw1 + 112;
        float* sw3 = sw2 + 256;
        float* sw4 = sw3 + 256;
        float* sc1 = sw4 + 128; float* sb1 = sc1 + 16;
        float* sc2 = sb1 + 16;  float* sb2 = sc2 + 16;
        float* sc3 = sb2 + 16;  float* sb3 = sc3 + 16;
        float* sb4 = sb3 + 16;
        if (t < 112) sw1[t] = w1[t];
        if (t < 256) { sw2[t] = w2[t]; sw3[t] = w3[t]; }
        if (t < 128) sw4[t] = w4[t];
        if (t < 16)  { sc1[t] = g1[t]*inv; sb1[t] = be1[t];
                       sc2[t] = g2[t]*inv; sb2[t] = be2[t];
                       sc3[t] = g3[t]*inv; sb3[t] = be3[t]; }
        if (t < 8)   sb4[t] = b4[t];
        __syncthreads();

        int p  = (bid - PMMA_BLKS)*512 + t;
        int k  = p & 31;
        int bn = p >> 5;
        int n  = bn & 1023;
        int b  = bn >> 10;

        float xf[7];
        float d2 = 0.f;
#pragma unroll
        for (int d = 0; d < 3; d++) {
            int base = ((b*3 + d)*NP + n)*KK;
            float x  = pts[base + k];
            float cx = pts[base];
            xf[d] = cx;
            float df = x - cx;
            xf[3 + d] = df;
            d2 += df*df;
        }
        xf[6] = sqrtf(d2);

        float h1[16];
#pragma unroll
        for (int i = 0; i < 16; i++) {
            float a = 0.f;
#pragma unroll
            for (int j = 0; j < 7; j++) a += sw1[i*7 + j]*xf[j];
            h1[i] = fmaxf(a*sc1[i] + sb1[i], 0.f);
        }
        float h2[16];
#pragma unroll
        for (int i = 0; i < 16; i++) {
            float a = 0.f;
#pragma unroll
            for (int j = 0; j < 16; j++) a += sw2[i*16 + j]*h1[j];
            h2[i] = fmaxf(a*sc2[i] + sb2[i], 0.f);
        }
        float h3[16];
#pragma unroll
        for (int i = 0; i < 16; i++) {
            float a = 0.f;
#pragma unroll
            for (int j = 0; j < 16; j++) a += sw3[i*16 + j]*h2[j];
            h3[i] = fmaxf(a*sc3[i] + sb3[i], 0.f);
        }
        float s[8];
#pragma unroll
        for (int i = 0; i < 8; i++) {
            float a = sb4[i];
#pragma unroll
            for (int j = 0; j < 16; j++) a += sw4[i*16 + j]*h3[j];
            s[i] = a;
        }
        float mx = s[0];
#pragma unroll
        for (int i = 1; i < 8; i++) mx = fmaxf(mx, s[i]);
        float sum = 0.f;
#pragma unroll
        for (int i = 0; i < 8; i++) { s[i] = __expf(s[i] - mx); sum += s[i]; }
        float r = 1.f / sum;
        float4 v0 = make_float4(s[0]*r, s[1]*r, s[2]*r, s[3]*r);
        float4 v1 = make_float4(s[4]*r, s[5]*r, s[6]*r, s[7]*r);
        ((float4*)(g_scores + p*8))[0] = v0;
        ((float4*)(g_scores + p*8))[1] = v1;
        return;
    }

    // ---- pmma: 4 batches (64 tiles) per block, W halves copied from g_Atop ----
    u32* sW   = spre;                 // 9216 u32 (256 rows x 36)
    u32* sCen = spre + 9216;          // 2560 u32 (4 batches x 32cp x 20)

    int w = t >> 5, lane = t & 31;
    int g = lane >> 2, tid = lane & 3;
    int tile00 = bid*64;
    int b = tile00 >> 10;
    int n00 = tile00 & 1023;

#pragma unroll
    for (int j = 0; j < 4; j++) {
        int u = t + j*512;
        int cp = u >> 6, tloc = u & 63;
        const float* fp0 = feat + ((b*64 + 2*cp)*NP + n00 + tloc)*KK;
        float va = fp0[0];
        float vb = fp0[NP*KK];
        sCen[(tloc >> 4)*640 + cp*20 + (tloc & 15)] = h2pack(va, vb);
    }

#pragma unroll
    for (int half = 0; half < 2; half++) {
        __syncthreads();
        // copy Wtop' rows [half*256, half*256+256) from g_Atop (float4)
        {
            const float4* src = (const float4*)(g_Atop + (size_t)half*256*72);
            float4* dst = (float4*)sW;
            for (int i = t; i < 2304; i += 512) dst[i] = src[i];
        }
        __syncthreads();

        int rowl = w*16 + g;
        int rowg = half*256 + rowl;
#pragma unroll
        for (int bt = 0; bt < 4; bt++) {
            int tile0 = tile00 + bt*16;
            const u32* sB = sCen + bt*640;
            u32 bfp[4][2][2];
#pragma unroll
            for (int ks = 0; ks < 4; ks++)
#pragma unroll
                for (int nt = 0; nt < 2; nt++) {
                    bfp[ks][nt][0] = sB[(ks*8 + tid)*20 + nt*8 + g];
                    bfp[ks][nt][1] = sB[(ks*8 + tid + 4)*20 + nt*8 + g];
                }
            float acc[2][4] = {{0,0,0,0},{0,0,0,0}};
#pragma unroll
            for (int ks = 0; ks < 4; ks++) {
                const u32* ar = sW + rowl*36 + ks*8 + tid;
                u32 a0 = ar[0], a2 = ar[4];
                u32 a1 = ar[8*36], a3 = ar[8*36 + 4];
                mma16(acc[0], a0, a1, a2, a3, bfp[ks][0][0], bfp[ks][0][1]);
                mma16(acc[1], a0, a1, a2, a3, bfp[ks][1][0], bfp[ks][1][1]);
            }
#pragma unroll
            for (int nt = 0; nt < 2; nt++) {
                int tcol = tile0 + nt*8 + 2*tid;
                g_P[(size_t)tcol*512 + rowg]           = acc[nt][0];
                g_P[(size_t)(tcol + 1)*512 + rowg]     = acc[nt][1];
                g_P[(size_t)tcol*512 + rowg + 8]       = acc[nt][2];
                g_P[(size_t)(tcol + 1)*512 + rowg + 8] = acc[nt][3];
            }
        }
    }
}

// ---------------- main: fp16 mma.sync GEMM (R10 verbatim) ----------------
// smem u32 layout:
//  sAu [0,18432)      A fp16: row (m*64+o) stride 36 u32 (=72 halves)
//  sFu [18432,20736)  B fp16: row cp (0..31) stride 72 u32 (2 tiles x 32 k)
//  sS  [20736,21312)  scores fp32 [tl][m*36 + k]
//  sP  [21312,22400)  P fp32 [tl][m*68 + o]
//  sBnb[22400,22464)
__global__ void __launch_bounds__(256, 2)
main_kernel(const float* __restrict__ feat, const float* __restrict__ bnb,
            float* __restrict__ out)
{
    extern __shared__ u32 smu[];
    u32*   sAu  = smu;
    u32*   sFu  = smu + 18432;
    float* sS   = (float*)(smu + 20736);
    float* sP   = (float*)(smu + 21312);
    float* sBnb = (float*)(smu + 22400);

    int t = threadIdx.x;
    int w = t >> 5, lane = t & 31;
    int g = lane >> 2, tid = lane & 3;
    int oc = w & 3;
    int khalf = w >> 2;

    // prologue: copy A (stationary) + bnb
#pragma unroll
    for (int i = 0; i < 18; i++)
        ((float4*)sAu)[t + i*256] = ((const float4*)g_Ah)[t + i*256];
    if (t < 64) sBnb[t] = bnb[t];

    int cnt = (NPASS - 1 - (int)blockIdx.x)/GRID_MAIN + 1;

    float4 rfa[2], rfb[2]; float rs[2]; float rp[4];

    auto stage_ldg = [&](int pp) {
        int tile0 = pp*2; int b = tile0 >> 10; int n0 = tile0 & 1023;
        const float* fbase = feat + ((b*64)*NP + n0)*KK;
#pragma unroll
        for (int j = 0; j < 2; j++) {
            int u = t + j*256;
            int tl = u >> 8, rem = u & 255;
            int cp = rem >> 3, q4 = rem & 7;
            const float* pa = fbase + (2*cp)*NP*KK + tl*KK + q4*4;
            rfa[j] = *(const float4*)pa;
            rfb[j] = *(const float4*)(pa + NP*KK);
        }
#pragma unroll
        for (int j = 0; j < 2; j++) rs[j] = g_scores[(size_t)tile0*256 + t + j*256];
#pragma unroll
        for (int j = 0; j < 4; j++) rp[j] = g_P[(size_t)tile0*512 + t + j*256];
    };
    auto stage_sts = [&]() {
#pragma unroll
        for (int j = 0; j < 2; j++) {
            int u = t + j*256;
            int tl = u >> 8, rem = u & 255;
            int cp = rem >> 3, q4 = rem & 7;
            u32* dst = sFu + cp*72 + tl*KK + q4*4;
            float4 fa = rfa[j], fb = rfb[j];
            dst[0] = h2pack(fa.x, fb.x);
            dst[1] = h2pack(fa.y, fb.y);
            dst[2] = h2pack(fa.z, fb.z);
            dst[3] = h2pack(fa.w, fb.w);
        }
#pragma unroll
        for (int j = 0; j < 2; j++) {
            int idx = t + j*256;            // tl*256 + k*8 + m
            int tl = idx >> 8, rem = idx & 255;
            int k = rem >> 3, m = rem & 7;
            sS[tl*288 + m*36 + k] = rs[j];
        }
#pragma unroll
        for (int j = 0; j < 4; j++) {
            int idx = t + j*256;            // tl*512 + m*64 + o
            int tl = idx >> 9, rem = idx & 511;
            int m = rem >> 6, o = rem & 63;
            sP[tl*544 + m*68 + o] = rp[j];
        }
    };

    stage_ldg(blockIdx.x);

    int cp2 = blockIdx.x;
    for (int it = 0; it < cnt; it++, cp2 += GRID_MAIN) {
        stage_sts();
        __syncthreads();
        if (it + 1 < cnt) stage_ldg(cp2 + GRID_MAIN);   // overlaps compute

        int tile0 = cp2*2;
        int b = tile0 >> 10, n0 = tile0 & 1023;
        int o0 = oc*16 + g;

        u32 bf[4][2][2][2];   // [ks][tl][nt][2]
#pragma unroll
        for (int ks = 0; ks < 4; ks++)
#pragma unroll
            for (int tl = 0; tl < 2; tl++)
#pragma unroll
                for (int nt = 0; nt < 2; nt++) {
                    int kcol = tl*KK + khalf*16 + nt*8 + g;
                    bf[ks][tl][nt][0] = sFu[(ks*8 + tid)*72 + kcol];
                    bf[ks][tl][nt][1] = sFu[(ks*8 + tid + 4)*72 + kcol];
                }

        float oacc[2][2][4];
#pragma unroll
        for (int tl = 0; tl < 2; tl++)
#pragma unroll
            for (int nt = 0; nt < 2; nt++)
#pragma unroll
                for (int r = 0; r < 4; r++) oacc[tl][nt][r] = 0.f;

#pragma unroll
        for (int mt = 0; mt < 8; mt++) {
            float acc[2][2][4];
#pragma unroll
            for (int tl = 0; tl < 2; tl++)
#pragma unroll
                for (int nt = 0; nt < 2; nt++)
#pragma unroll
                    for (int r = 0; r < 4; r++) acc[tl][nt][r] = 0.f;

            int row = mt*64 + o0;
#pragma unroll
            for (int ks = 0; ks < 4; ks++) {
                const u32* ar = sAu + row*36 + ks*8 + tid;
                u32 a0 = ar[0], a2 = ar[4];
                u32 a1 = ar[8*36], a3 = ar[8*36 + 4];
                mma16(acc[0][0], a0, a1, a2, a3, bf[ks][0][0][0], bf[ks][0][0][1]);
                mma16(acc[0][1], a0, a1, a2, a3, bf[ks][0][1][0], bf[ks][0][1][1]);
                mma16(acc[1][0], a0, a1, a2, a3, bf[ks][1][0][0], bf[ks][1][0][1]);
                mma16(acc[1][1], a0, a1, a2, a3, bf[ks][1][1][0], bf[ks][1][1][1]);
            }
#pragma unroll
            for (int tl = 0; tl < 2; tl++) {
                const float* srow = sS + tl*288 + mt*36 + khalf*16 + tid*2;
                float2 s0 = *(const float2*)(srow);
                float2 s1 = *(const float2*)(srow + 8);
                float p0 = sP[tl*544 + mt*68 + o0];
                float p1 = sP[tl*544 + mt*68 + o0 + 8];
                oacc[tl][0][0] += (acc[tl][0][0] - p0)*s0.x;
                oacc[tl][0][1] += (acc[tl][0][1] - p0)*s0.y;
                oacc[tl][0][2] += (acc[tl][0][2] - p1)*s0.x;
                oacc[tl][0][3] += (acc[tl][0][3] - p1)*s0.y;
                oacc[tl][1][0] += (acc[tl][1][0] - p0)*s1.x;
                oacc[tl][1][1] += (acc[tl][1][1] - p0)*s1.y;
                oacc[tl][1][2] += (acc[tl][1][2] - p1)*s1.x;
                oacc[tl][1][3] += (acc[tl][1][3] - p1)*s1.y;
            }
        }

        float b0 = sBnb[o0], b1 = sBnb[o0 + 8];
#pragma unroll
        for (int tl = 0; tl < 2; tl++) {
            int n = n0 + tl;
            float* ob = out + ((b*64 + o0)*NP + n)*KK + khalf*16 + tid*2;
#pragma unroll
            for (int nt = 0; nt < 2; nt++) {
                float2 r0 = make_float2(fmaxf(oacc[tl][nt][0] + b0, 0.f),
                                        fmaxf(oacc[tl][nt][1] + b0, 0.f));
                float2 r1 = make_float2(fmaxf(oacc[tl][nt][2] + b1, 0.f),
                                        fmaxf(oacc[tl][nt][3] + b1, 0.f));
                *(float2*)(ob + nt*8) = r0;
                *(float2*)(ob + 8*NP*KK + nt*8) = r1;
            }
        }
        __syncthreads();
    }
}

// ---------------- launch ----------------
extern "C" void kernel_launch(void* const* d_in, const int* in_sizes, int n_in,
                              void* d_out, int out_size)
{
    const float* features = (const float*)d_in[0];
    const float* pts      = (const float*)d_in[1];
    const float* w1  = (const float*)d_in[2];
    const float* g1  = (const float*)d_in[3];
    const float* be1 = (const float*)d_in[4];
    const float* w2  = (const float*)d_in[5];
    const float* g2  = (const float*)d_in[6];
    const float* be2 = (const float*)d_in[7];
    const float* w3  = (const float*)d_in[8];
    const float* g3  = (const float*)d_in[9];
    const float* be3 = (const float*)d_in[10];
    const float* w4  = (const float*)d_in[11];
    const float* b4  = (const float*)d_in[12];
    const float* wb  = (const float*)d_in[13];
    const float* bng = (const float*)d_in[14];
    const float* bnb = (const float*)d_in[15];
    float* out = (float*)d_out;

    const int MAIN_SMEM = 22464*4;           // 89856
    cudaFuncSetAttribute(main_kernel, cudaFuncAttributeMaxDynamicSharedMemorySize, MAIN_SMEM);

    prep_kernel<<<128, 256>>>(wb, bng);
    pre_kernel<<<PRE_GRID, 512>>>(features, pts,
        w1, g1, be1, w2, g2, be2, w3, g3, be3, w4, b4);
    main_kernel<<<GRID_MAIN, 256, MAIN_SMEM>>>(features, bnb, out);
}